// round 1
// baseline (speedup 1.0000x reference)
#include <cuda_runtime.h>

#define N_NODES 100000
#define N_EDGES 1600000
#define D 128
#define NLAB 1024
#define SCAN_BS 512
#define NB_SCAN ((N_NODES + SCAN_BS - 1) / SCAN_BS)   // 196

// ---------------- device scratch (no allocations allowed) ----------------
__device__ int   g_is64;
__device__ int   g_cnt[N_NODES];          // histogram, then cursor
__device__ int   g_rowoff[N_NODES + 1];
__device__ int   g_part[256];
__device__ int   g_adj[N_EDGES];
__device__ float g_t[(size_t)N_NODES * D];
__device__ float g_z[(size_t)N_NODES * D];
__device__ float g_h1[(size_t)N_NODES * D];
__device__ float g_h2[(size_t)N_NODES * D];

// ---------------- index dtype handling ----------------
__device__ __forceinline__ int load_idx(const void* p, int i, int is64) {
    if (is64) return (int)((const unsigned long long*)p)[i];
    return ((const int*)p)[i];
}

// Detect int64 vs int32 indices: if int64, every odd 32-bit word (high half)
// is zero. For int32 data (uniform in [0,1e5)), 4096 consecutive odd-position
// values being all zero is impossible in practice.
__global__ void k_detect(const int* __restrict__ src32) {
    __shared__ int nz;
    if (threadIdx.x == 0) nz = 0;
    __syncthreads();
    int found = 0;
    for (int i = threadIdx.x; i < 4096; i += blockDim.x)
        if (src32[2 * i + 1] != 0) found = 1;
    if (found) atomicOr(&nz, 1);
    __syncthreads();
    if (threadIdx.x == 0) g_is64 = nz ? 0 : 1;
}

__global__ void k_init() {
    int i = blockIdx.x * blockDim.x + threadIdx.x;
    if (i < N_NODES) g_cnt[i] = 0;
}

__global__ void k_hist(const void* __restrict__ dst) {
    int e = blockIdx.x * blockDim.x + threadIdx.x;
    if (e >= N_EDGES) return;
    int is64 = g_is64;
    int d = load_idx(dst, e, is64);
    atomicAdd(&g_cnt[d], 1);
}

__global__ void k_scan1() {
    __shared__ int s[SCAN_BS];
    int tid = threadIdx.x;
    int i = blockIdx.x * SCAN_BS + tid;
    int v = (i < N_NODES) ? g_cnt[i] : 0;
    s[tid] = v;
    __syncthreads();
#pragma unroll
    for (int off = 1; off < SCAN_BS; off <<= 1) {
        int t = (tid >= off) ? s[tid - off] : 0;
        __syncthreads();
        s[tid] += t;
        __syncthreads();
    }
    if (i < N_NODES) g_rowoff[i] = s[tid] - v;     // exclusive within block
    if (tid == SCAN_BS - 1) g_part[blockIdx.x] = s[SCAN_BS - 1];
}

__global__ void k_scan2() {
    __shared__ int s[256];
    int tid = threadIdx.x;
    int v = (tid < NB_SCAN) ? g_part[tid] : 0;
    s[tid] = v;
    __syncthreads();
#pragma unroll
    for (int off = 1; off < 256; off <<= 1) {
        int t = (tid >= off) ? s[tid - off] : 0;
        __syncthreads();
        s[tid] += t;
        __syncthreads();
    }
    if (tid < NB_SCAN) g_part[tid] = s[tid] - v;   // exclusive
}

__global__ void k_scan3() {
    int i = blockIdx.x * blockDim.x + threadIdx.x;
    if (i < N_NODES) {
        int off = g_rowoff[i] + g_part[i >> 9];
        g_rowoff[i] = off;
        g_cnt[i] = off;                            // cursor copy
    }
    if (i == 0) g_rowoff[N_NODES] = N_EDGES;
}

__global__ void k_scatter(const void* __restrict__ src, const void* __restrict__ dst) {
    int e = blockIdx.x * blockDim.x + threadIdx.x;
    if (e >= N_EDGES) return;
    int is64 = g_is64;
    int s = load_idx(src, e, is64);
    int d = load_idx(dst, e, is64);
    int pos = atomicAdd(&g_cnt[d], 1);
    g_adj[pos] = s;
}

// t[node] = (1+eps)*h[node] + sum_{e: dst==node} h[src[e]]
// one warp per node; lane handles 4 floats (float4) of the 128-wide row.
__global__ void __launch_bounds__(256) k_agg(const float* __restrict__ h,
                                             const float* __restrict__ eps_p,
                                             float* __restrict__ outt) {
    int w = blockIdx.x * 8 + (threadIdx.x >> 5);
    int lane = threadIdx.x & 31;
    if (w >= N_NODES) return;
    float ep1 = 1.0f + *eps_p;
    const float4* h4 = (const float4*)h;
    float4 a0 = make_float4(0.f, 0.f, 0.f, 0.f);
    float4 a1 = make_float4(0.f, 0.f, 0.f, 0.f);
    int e = g_rowoff[w];
    int end = g_rowoff[w + 1];
    for (; e + 2 <= end; e += 2) {
        int s0 = g_adj[e], s1 = g_adj[e + 1];
        float4 v0 = h4[(size_t)s0 * 32 + lane];
        float4 v1 = h4[(size_t)s1 * 32 + lane];
        a0.x += v0.x; a0.y += v0.y; a0.z += v0.z; a0.w += v0.w;
        a1.x += v1.x; a1.y += v1.y; a1.z += v1.z; a1.w += v1.w;
    }
    if (e < end) {
        int s0 = g_adj[e];
        float4 v0 = h4[(size_t)s0 * 32 + lane];
        a0.x += v0.x; a0.y += v0.y; a0.z += v0.z; a0.w += v0.w;
    }
    float4 self = h4[(size_t)w * 32 + lane];
    float4 r;
    r.x = ep1 * self.x + a0.x + a1.x;
    r.y = ep1 * self.y + a0.y + a1.y;
    r.z = ep1 * self.z + a0.z + a1.z;
    r.w = ep1 * self.w + a0.w + a1.w;
    ((float4*)outt)[(size_t)w * 32 + lane] = r;
}

// ---------------- tiled SGEMM: C[M,LDN-chunk] = f(A[M,128] @ W[128,LDN]) ----------------
// 128x128 block tile, 8x8 microtile, 256 threads, K=128 in 4 chunks of 32.
// RELU: relu after bias. ADDSRC: add Z (stride LDN) after relu. POOL: A := 0.5*(A+A2).
template <int RELU, int ADDSRC, int POOL, int LDN>
__global__ void __launch_bounds__(256) k_gemm(const float* __restrict__ A,
                                              const float* __restrict__ A2,
                                              const float* __restrict__ W,
                                              const float* __restrict__ bias,
                                              const float* __restrict__ Z,
                                              float* __restrict__ Cout, int M) {
    __shared__ float As[128][33];   // [m][k-in-chunk], pad to kill bank conflicts
    __shared__ float Bs[32][128];   // [k-in-chunk][n]

    int tid = threadIdx.x;
    int tx = tid & 15;              // 16 col groups
    int ty = tid >> 4;              // 16 row groups
    int m0 = blockIdx.x * 128;
    int n0 = blockIdx.y * 128;

    float acc[8][8];
#pragma unroll
    for (int i = 0; i < 8; i++)
#pragma unroll
        for (int j = 0; j < 8; j++) acc[i][j] = 0.f;

    const float4* A4 = (const float4*)A;
    const float4* A24 = (const float4*)A2;

#pragma unroll 1
    for (int kc = 0; kc < 4; kc++) {
        // ---- load A chunk: 128 rows x 32 k  (1024 float4) ----
#pragma unroll
        for (int p = 0; p < 4; p++) {
            int idx = p * 256 + tid;        // 0..1023
            int m = idx >> 3;
            int f4 = idx & 7;
            int row = m0 + m;
            float4 v = make_float4(0.f, 0.f, 0.f, 0.f);
            if (row < M) {
                size_t gi = (size_t)row * 32 + kc * 8 + f4;
                v = A4[gi];
                if (POOL) {
                    float4 u = A24[gi];
                    v.x = 0.5f * (v.x + u.x);
                    v.y = 0.5f * (v.y + u.y);
                    v.z = 0.5f * (v.z + u.z);
                    v.w = 0.5f * (v.w + u.w);
                }
            }
            As[m][f4 * 4 + 0] = v.x;
            As[m][f4 * 4 + 1] = v.y;
            As[m][f4 * 4 + 2] = v.z;
            As[m][f4 * 4 + 3] = v.w;
        }
        // ---- load B chunk: 32 k x 128 n ----
#pragma unroll
        for (int p = 0; p < 4; p++) {
            int idx = p * 256 + tid;        // 0..1023
            int kk = idx >> 5;
            int f4 = idx & 31;
            const float4* Wr = (const float4*)(W + (size_t)(kc * 32 + kk) * LDN + n0);
            *(float4*)&Bs[kk][f4 * 4] = Wr[f4];
        }
        __syncthreads();

#pragma unroll 8
        for (int kk = 0; kk < 32; kk++) {
            float a[8];
#pragma unroll
            for (int i = 0; i < 8; i++) a[i] = As[ty * 8 + i][kk];
            float4 b0 = *(const float4*)&Bs[kk][tx * 4];
            float4 b1 = *(const float4*)&Bs[kk][64 + tx * 4];
            float b[8] = {b0.x, b0.y, b0.z, b0.w, b1.x, b1.y, b1.z, b1.w};
#pragma unroll
            for (int i = 0; i < 8; i++)
#pragma unroll
                for (int j = 0; j < 8; j++) acc[i][j] += a[i] * b[j];
        }
        __syncthreads();
    }

    // ---- epilogue ----
    float4 bv0 = *(const float4*)(bias + n0 + tx * 4);
    float4 bv1 = *(const float4*)(bias + n0 + 64 + tx * 4);
    float bb[8] = {bv0.x, bv0.y, bv0.z, bv0.w, bv1.x, bv1.y, bv1.z, bv1.w};

#pragma unroll
    for (int i = 0; i < 8; i++) {
        int row = m0 + ty * 8 + i;
        if (row >= M) continue;
#pragma unroll
        for (int g = 0; g < 2; g++) {
            int col = n0 + g * 64 + tx * 4;
            float4 r;
            r.x = acc[i][g * 4 + 0] + bb[g * 4 + 0];
            r.y = acc[i][g * 4 + 1] + bb[g * 4 + 1];
            r.z = acc[i][g * 4 + 2] + bb[g * 4 + 2];
            r.w = acc[i][g * 4 + 3] + bb[g * 4 + 3];
            if (RELU) {
                r.x = fmaxf(r.x, 0.f);
                r.y = fmaxf(r.y, 0.f);
                r.z = fmaxf(r.z, 0.f);
                r.w = fmaxf(r.w, 0.f);
            }
            if (ADDSRC) {
                float4 z = *(const float4*)(Z + (size_t)row * LDN + col);
                r.x += z.x; r.y += z.y; r.z += z.z; r.w += z.w;
            }
            *(float4*)(Cout + (size_t)row * LDN + col) = r;
        }
    }
}

// ---------------- launcher ----------------
extern "C" void kernel_launch(void* const* d_in, const int* in_sizes, int n_in,
                              void* d_out, int out_size) {
    const float* inputs = (const float*)d_in[0];
    const void*  src    = d_in[1];
    const void*  dst    = d_in[2];
    const float* eps1   = (const float*)d_in[3];
    const float* W1     = (const float*)d_in[4];
    const float* b1     = (const float*)d_in[5];
    const float* rW1    = (const float*)d_in[6];
    const float* rb1    = (const float*)d_in[7];
    const float* eps2   = (const float*)d_in[8];
    const float* W2     = (const float*)d_in[9];
    const float* b2     = (const float*)d_in[10];
    const float* rW2    = (const float*)d_in[11];
    const float* rb2    = (const float*)d_in[12];
    const float* linW   = (const float*)d_in[13];
    const float* linb   = (const float*)d_in[14];
    float* out = (float*)d_out;

    float *t, *z, *h1, *h2;
    cudaGetSymbolAddress((void**)&t,  g_t);
    cudaGetSymbolAddress((void**)&z,  g_z);
    cudaGetSymbolAddress((void**)&h1, g_h1);
    cudaGetSymbolAddress((void**)&h2, g_h2);

    const int M = N_NODES;
    const int EB = (N_EDGES + 255) / 256;
    const int NBn = (N_NODES + 255) / 256;

    // CSR build (deterministic work each call; rebuilt so graph replays are valid)
    k_init<<<NBn, 256>>>();
    k_detect<<<1, 256>>>((const int*)src);
    k_hist<<<EB, 256>>>(dst);
    k_scan1<<<NB_SCAN, SCAN_BS>>>();
    k_scan2<<<1, 256>>>();
    k_scan3<<<NBn, 256>>>();
    k_scatter<<<EB, 256>>>(src, dst);

    const int AGG_B = (N_NODES + 7) / 8;
    const int GM = (M + 127) / 128;

    // Layer 1
    k_agg<<<AGG_B, 256>>>(inputs, eps1, t);
    k_gemm<1, 0, 0, 128><<<dim3(GM, 1), 256>>>(t, nullptr, W1, b1, nullptr, z, M);
    k_gemm<1, 1, 0, 128><<<dim3(GM, 1), 256>>>(z, nullptr, rW1, rb1, z, h1, M);
    // Layer 2
    k_agg<<<AGG_B, 256>>>(h1, eps2, t);
    k_gemm<1, 0, 0, 128><<<dim3(GM, 1), 256>>>(t, nullptr, W2, b2, nullptr, z, M);
    k_gemm<1, 1, 0, 128><<<dim3(GM, 1), 256>>>(z, nullptr, rW2, rb2, z, h2, M);
    // Pool + head: out = 0.5*(h1+h2) @ linW + linb
    k_gemm<0, 0, 1, NLAB><<<dim3(GM, NLAB / 128), 256>>>(h1, h2, linW, linb, nullptr, out, M);
}

// round 9
// speedup vs baseline: 1.1905x; 1.1905x over previous
#include <cuda_runtime.h>
#include <cuda_bf16.h>
#include <cstdint>

#define N_NODES 100000
#define N_EDGES 1600000
#define D 128
#define NLAB 1024
#define SCAN_BS 512
#define NB_SCAN ((N_NODES + SCAN_BS - 1) / SCAN_BS)   // 196

// ---------------- device scratch (no allocations allowed) ----------------
__device__ int   g_is64;
__device__ int   g_cnt[N_NODES];          // histogram, then cursor
__device__ int   g_rowoff[N_NODES + 1];
__device__ int   g_part[256];
__device__ int   g_adj[N_EDGES];
__device__ float g_t[(size_t)N_NODES * D];
__device__ float g_z[(size_t)N_NODES * D];
__device__ float g_h1[(size_t)N_NODES * D];
__device__ float g_h2[(size_t)N_NODES * D];

// ---------------- index dtype handling ----------------
__device__ __forceinline__ int load_idx(const void* p, int i, int is64) {
    if (is64) return (int)((const unsigned long long*)p)[i];
    return ((const int*)p)[i];
}

__global__ void k_detect(const int* __restrict__ src32) {
    __shared__ int nz;
    if (threadIdx.x == 0) nz = 0;
    __syncthreads();
    int found = 0;
    for (int i = threadIdx.x; i < 4096; i += blockDim.x)
        if (src32[2 * i + 1] != 0) found = 1;
    if (found) atomicOr(&nz, 1);
    __syncthreads();
    if (threadIdx.x == 0) g_is64 = nz ? 0 : 1;
}

__global__ void k_init() {
    int i = blockIdx.x * blockDim.x + threadIdx.x;
    if (i < N_NODES) g_cnt[i] = 0;
}

__global__ void k_hist(const void* __restrict__ dst) {
    int e = blockIdx.x * blockDim.x + threadIdx.x;
    if (e >= N_EDGES) return;
    int is64 = g_is64;
    int d = load_idx(dst, e, is64);
    atomicAdd(&g_cnt[d], 1);
}

__global__ void k_scan1() {
    __shared__ int s[SCAN_BS];
    int tid = threadIdx.x;
    int i = blockIdx.x * SCAN_BS + tid;
    int v = (i < N_NODES) ? g_cnt[i] : 0;
    s[tid] = v;
    __syncthreads();
#pragma unroll
    for (int off = 1; off < SCAN_BS; off <<= 1) {
        int t = (tid >= off) ? s[tid - off] : 0;
        __syncthreads();
        s[tid] += t;
        __syncthreads();
    }
    if (i < N_NODES) g_rowoff[i] = s[tid] - v;
    if (tid == SCAN_BS - 1) g_part[blockIdx.x] = s[SCAN_BS - 1];
}

__global__ void k_scan2() {
    __shared__ int s[256];
    int tid = threadIdx.x;
    int v = (tid < NB_SCAN) ? g_part[tid] : 0;
    s[tid] = v;
    __syncthreads();
#pragma unroll
    for (int off = 1; off < 256; off <<= 1) {
        int t = (tid >= off) ? s[tid - off] : 0;
        __syncthreads();
        s[tid] += t;
        __syncthreads();
    }
    if (tid < NB_SCAN) g_part[tid] = s[tid] - v;
}

__global__ void k_scan3() {
    int i = blockIdx.x * blockDim.x + threadIdx.x;
    if (i < N_NODES) {
        int off = g_rowoff[i] + g_part[i >> 9];
        g_rowoff[i] = off;
        g_cnt[i] = off;
    }
    if (i == 0) g_rowoff[N_NODES] = N_EDGES;
}

__global__ void k_scatter(const void* __restrict__ src, const void* __restrict__ dst) {
    int e = blockIdx.x * blockDim.x + threadIdx.x;
    if (e >= N_EDGES) return;
    int is64 = g_is64;
    int s = load_idx(src, e, is64);
    int d = load_idx(dst, e, is64);
    int pos = atomicAdd(&g_cnt[d], 1);
    g_adj[pos] = s;
}

// t[node] = (1+eps)*h[node] + sum_{e: dst==node} h[src[e]]
__global__ void __launch_bounds__(256) k_agg(const float* __restrict__ h,
                                             const float* __restrict__ eps_p,
                                             float* __restrict__ outt) {
    int w = blockIdx.x * 8 + (threadIdx.x >> 5);
    int lane = threadIdx.x & 31;
    if (w >= N_NODES) return;
    float ep1 = 1.0f + *eps_p;
    const float4* h4 = (const float4*)h;
    float4 a0 = make_float4(0.f, 0.f, 0.f, 0.f);
    float4 a1 = make_float4(0.f, 0.f, 0.f, 0.f);
    int e = g_rowoff[w];
    int end = g_rowoff[w + 1];
    for (; e + 2 <= end; e += 2) {
        int s0 = g_adj[e], s1 = g_adj[e + 1];
        float4 v0 = h4[(size_t)s0 * 32 + lane];
        float4 v1 = h4[(size_t)s1 * 32 + lane];
        a0.x += v0.x; a0.y += v0.y; a0.z += v0.z; a0.w += v0.w;
        a1.x += v1.x; a1.y += v1.y; a1.z += v1.z; a1.w += v1.w;
    }
    if (e < end) {
        int s0 = g_adj[e];
        float4 v0 = h4[(size_t)s0 * 32 + lane];
        a0.x += v0.x; a0.y += v0.y; a0.z += v0.z; a0.w += v0.w;
    }
    float4 self = h4[(size_t)w * 32 + lane];
    float4 r;
    r.x = ep1 * self.x + a0.x + a1.x;
    r.y = ep1 * self.y + a0.y + a1.y;
    r.z = ep1 * self.z + a0.z + a1.z;
    r.w = ep1 * self.w + a0.w + a1.w;
    ((float4*)outt)[(size_t)w * 32 + lane] = r;
}

// ================= mma.sync bf16-split GEMM (baseline PTX, no 'a' features) ==
// C[M, 128-slice of LDN] = epilogue(A[M,128] @ W[128,LDN])
// A,W split into bf16 hi/lo; D = Ahi*Whi + Ahi*Wlo + Alo*Whi (fp32 reg accum).
// Block: 128x128 tile, 256 threads (8 warps as 2x4), warp tile 64x32.
// mma.sync.aligned.m16n8k16.row.col.f32.bf16.bf16.f32
// SMEM: 4 planes, row-major, 136-bf16 (272 B) row stride:
//   A_hi [128 m][128 k], A_lo, B_hi [128 k][128 n], B_lo.
#define PADB 272                    // bytes per row (136 bf16, 68 words)
#define SA_HI 0
#define SA_LO 34816
#define SB_HI 69632
#define SB_LO 104448
#define SMEM_GEMM 139264

__device__ __forceinline__ void split_bf16(float x, uint16_t& hi, uint16_t& lo) {
    __nv_bfloat16 h = __float2bfloat16(x);
    __nv_bfloat16 l = __float2bfloat16(x - __bfloat162float(h));
    hi = __bfloat16_as_ushort(h);
    lo = __bfloat16_as_ushort(l);
}

__device__ __forceinline__ void mma16816(float* c, const uint32_t* a, const uint32_t* b) {
    asm volatile(
        "mma.sync.aligned.m16n8k16.row.col.f32.bf16.bf16.f32 "
        "{%0,%1,%2,%3}, {%4,%5,%6,%7}, {%8,%9}, {%0,%1,%2,%3};"
        : "+f"(c[0]), "+f"(c[1]), "+f"(c[2]), "+f"(c[3])
        : "r"(a[0]), "r"(a[1]), "r"(a[2]), "r"(a[3]), "r"(b[0]), "r"(b[1]));
}

template <int RELU, int ADDSRC, int POOL, int LDN>
__global__ void __launch_bounds__(256) k_gemm_mma(const float* __restrict__ A,
                                                  const float* __restrict__ A2,
                                                  const float* __restrict__ W,
                                                  const float* __restrict__ bias,
                                                  const float* __restrict__ Z,
                                                  float* __restrict__ C, int M) {
    extern __shared__ char sm[];
    const int tid = threadIdx.x;
    const int wid = tid >> 5;
    const int lane = tid & 31;
    const int qid = lane >> 2;            // 0..7 (row group)
    const int qtr = lane & 3;             // 0..3 (thread-in-group)
    const int m0 = blockIdx.x * 128;
    const int n0 = blockIdx.y * 128;
    const int wm = (wid >> 2) * 64;       // warp m offset
    const int wn = (wid & 3) * 32;        // warp n offset

    // ---- fill A planes: [m][k] row-major, split fp32 -> bf16 hi/lo ----
    {
        const float4* A4 = (const float4*)A;
        const float4* A24 = (const float4*)A2;
#pragma unroll 4
        for (int p = 0; p < 16; p++) {
            int idx = p * 256 + tid;      // 0..4095
            int row = idx >> 5;
            int c4 = idx & 31;
            float4 v = make_float4(0.f, 0.f, 0.f, 0.f);
            if (m0 + row < M) {
                size_t gi = (size_t)(m0 + row) * 32 + c4;
                v = A4[gi];
                if (POOL) {
                    float4 u = A24[gi];
                    v.x = 0.5f * (v.x + u.x);
                    v.y = 0.5f * (v.y + u.y);
                    v.z = 0.5f * (v.z + u.z);
                    v.w = 0.5f * (v.w + u.w);
                }
            }
            uint16_t h0, h1, h2, h3, l0, l1, l2, l3;
            split_bf16(v.x, h0, l0);
            split_bf16(v.y, h1, l1);
            split_bf16(v.z, h2, l2);
            split_bf16(v.w, h3, l3);
            uint2 hp = make_uint2((uint32_t)h0 | ((uint32_t)h1 << 16),
                                  (uint32_t)h2 | ((uint32_t)h3 << 16));
            uint2 lp = make_uint2((uint32_t)l0 | ((uint32_t)l1 << 16),
                                  (uint32_t)l2 | ((uint32_t)l3 << 16));
            *(uint2*)(sm + SA_HI + row * PADB + c4 * 8) = hp;
            *(uint2*)(sm + SA_LO + row * PADB + c4 * 8) = lp;
        }
    }
    // ---- fill B planes: [k][n] row-major from W[k][n0..n0+127] ----
    {
#pragma unroll 4
        for (int p = 0; p < 16; p++) {
            int idx = p * 256 + tid;      // 0..4095
            int k = idx >> 5;
            int c4 = idx & 31;
            float4 w = *(const float4*)(W + (size_t)k * LDN + n0 + c4 * 4);
            uint16_t h0, h1, h2, h3, l0, l1, l2, l3;
            split_bf16(w.x, h0, l0);
            split_bf16(w.y, h1, l1);
            split_bf16(w.z, h2, l2);
            split_bf16(w.w, h3, l3);
            uint2 hp = make_uint2((uint32_t)h0 | ((uint32_t)h1 << 16),
                                  (uint32_t)h2 | ((uint32_t)h3 << 16));
            uint2 lp = make_uint2((uint32_t)l0 | ((uint32_t)l1 << 16),
                                  (uint32_t)l2 | ((uint32_t)l3 << 16));
            *(uint2*)(sm + SB_HI + k * PADB + c4 * 8) = hp;
            *(uint2*)(sm + SB_LO + k * PADB + c4 * 8) = lp;
        }
    }
    __syncthreads();

    float acc[4][4][4];
#pragma unroll
    for (int i = 0; i < 4; i++)
#pragma unroll
        for (int j = 0; j < 4; j++)
#pragma unroll
            for (int r = 0; r < 4; r++) acc[i][j][r] = 0.f;

#pragma unroll
    for (int ks = 0; ks < 8; ks++) {
        const int kb = ks * 16;
        // B fragments: b reg holds bf16 pair (k, k+1) for column n
        uint32_t bh[4][2], bl[4][2];
#pragma unroll
        for (int j = 0; j < 4; j++) {
#pragma unroll
            for (int r = 0; r < 2; r++) {
                int n = wn + j * 8 + qid;
                int k = kb + r * 8 + qtr * 2;
                uint32_t h_a = *(const uint16_t*)(sm + SB_HI + k * PADB + n * 2);
                uint32_t h_b = *(const uint16_t*)(sm + SB_HI + (k + 1) * PADB + n * 2);
                bh[j][r] = h_a | (h_b << 16);
                uint32_t l_a = *(const uint16_t*)(sm + SB_LO + k * PADB + n * 2);
                uint32_t l_b = *(const uint16_t*)(sm + SB_LO + (k + 1) * PADB + n * 2);
                bl[j][r] = l_a | (l_b << 16);
            }
        }
#pragma unroll
        for (int i = 0; i < 4; i++) {
            uint32_t ah[4], al[4];
#pragma unroll
            for (int r = 0; r < 4; r++) {
                int row = wm + i * 16 + (r & 1) * 8 + qid;
                int kc = kb + (r >> 1) * 8 + qtr * 2;
                ah[r] = *(const uint32_t*)(sm + SA_HI + row * PADB + kc * 2);
                al[r] = *(const uint32_t*)(sm + SA_LO + row * PADB + kc * 2);
            }
#pragma unroll
            for (int j = 0; j < 4; j++) {
                mma16816(acc[i][j], ah, bh[j]);   // hi*hi
                mma16816(acc[i][j], ah, bl[j]);   // hi*lo
                mma16816(acc[i][j], al, bh[j]);   // lo*hi
            }
        }
    }

    // ---- epilogue: bias (+relu) (+residual add), direct global store ----
#pragma unroll
    for (int i = 0; i < 4; i++) {
#pragma unroll
        for (int h = 0; h < 2; h++) {
            int row = m0 + wm + i * 16 + h * 8 + qid;
            if (row >= M) continue;
#pragma unroll
            for (int j = 0; j < 4; j++) {
                int col = n0 + wn + j * 8 + qtr * 2;
                float v0 = acc[i][j][h * 2 + 0] + bias[col];
                float v1 = acc[i][j][h * 2 + 1] + bias[col + 1];
                if (RELU) {
                    v0 = fmaxf(v0, 0.f);
                    v1 = fmaxf(v1, 0.f);
                }
                if (ADDSRC) {
                    float2 z = *(const float2*)(Z + (size_t)row * LDN + col);
                    v0 += z.x;
                    v1 += z.y;
                }
                float2 st = make_float2(v0, v1);
                *(float2*)(C + (size_t)row * LDN + col) = st;
            }
        }
    }
}

// ---------------- launcher ----------------
extern "C" void kernel_launch(void* const* d_in, const int* in_sizes, int n_in,
                              void* d_out, int out_size) {
    const float* inputs = (const float*)d_in[0];
    const void*  src    = d_in[1];
    const void*  dst    = d_in[2];
    const float* eps1   = (const float*)d_in[3];
    const float* W1     = (const float*)d_in[4];
    const float* b1     = (const float*)d_in[5];
    const float* rW1    = (const float*)d_in[6];
    const float* rb1    = (const float*)d_in[7];
    const float* eps2   = (const float*)d_in[8];
    const float* W2     = (const float*)d_in[9];
    const float* b2     = (const float*)d_in[10];
    const float* rW2    = (const float*)d_in[11];
    const float* rb2    = (const float*)d_in[12];
    const float* linW   = (const float*)d_in[13];
    const float* linb   = (const float*)d_in[14];
    float* out = (float*)d_out;

    float *t, *z, *h1, *h2;
    cudaGetSymbolAddress((void**)&t,  g_t);
    cudaGetSymbolAddress((void**)&z,  g_z);
    cudaGetSymbolAddress((void**)&h1, g_h1);
    cudaGetSymbolAddress((void**)&h2, g_h2);

    const int M = N_NODES;
    const int EB = (N_EDGES + 255) / 256;
    const int NBn = (N_NODES + 255) / 256;

    cudaFuncSetAttribute(k_gemm_mma<1, 0, 0, 128>,
                         cudaFuncAttributeMaxDynamicSharedMemorySize, SMEM_GEMM);
    cudaFuncSetAttribute(k_gemm_mma<1, 1, 0, 128>,
                         cudaFuncAttributeMaxDynamicSharedMemorySize, SMEM_GEMM);
    cudaFuncSetAttribute(k_gemm_mma<0, 0, 1, NLAB>,
                         cudaFuncAttributeMaxDynamicSharedMemorySize, SMEM_GEMM);

    // CSR build
    k_init<<<NBn, 256>>>();
    k_detect<<<1, 256>>>((const int*)src);
    k_hist<<<EB, 256>>>(dst);
    k_scan1<<<NB_SCAN, SCAN_BS>>>();
    k_scan2<<<1, 256>>>();
    k_scan3<<<NBn, 256>>>();
    k_scatter<<<EB, 256>>>(src, dst);

    const int AGG_B = (N_NODES + 7) / 8;
    const int GM = (M + 127) / 128;   // 782

    // Layer 1
    k_agg<<<AGG_B, 256>>>(inputs, eps1, t);
    k_gemm_mma<1, 0, 0, 128><<<dim3(GM, 1), 256, SMEM_GEMM>>>(t, nullptr, W1, b1, nullptr, z, M);
    k_gemm_mma<1, 1, 0, 128><<<dim3(GM, 1), 256, SMEM_GEMM>>>(z, nullptr, rW1, rb1, z, h1, M);
    // Layer 2
    k_agg<<<AGG_B, 256>>>(h1, eps2, t);
    k_gemm_mma<1, 0, 0, 128><<<dim3(GM, 1), 256, SMEM_GEMM>>>(t, nullptr, W2, b2, nullptr, z, M);
    k_gemm_mma<1, 1, 0, 128><<<dim3(GM, 1), 256, SMEM_GEMM>>>(z, nullptr, rW2, rb2, z, h2, M);
    // Pool + head: out = 0.5*(h1+h2) @ linW + linb
    k_gemm_mma<0, 0, 1, NLAB><<<dim3(GM, NLAB / 128), 256, SMEM_GEMM>>>(h1, h2, linW, linb, nullptr, out, M);
}

// round 11
// speedup vs baseline: 1.6639x; 1.3977x over previous
#include <cuda_runtime.h>
#include <cuda_fp16.h>
#include <cstdint>

#define N_NODES 100000
#define N_EDGES 1600000
#define D 128
#define NLAB 1024
#define SCAN_BS 512
#define NB_SCAN ((N_NODES + SCAN_BS - 1) / SCAN_BS)   // 196

// ---------------- device scratch (no allocations allowed) ----------------
__device__ int   g_is64;
__device__ int   g_cnt[N_NODES];          // histogram, then cursor
__device__ int   g_rowoff[N_NODES + 1];
__device__ int   g_part[256];
__device__ int   g_adj[N_EDGES];
__device__ float g_t[(size_t)N_NODES * D];
__device__ float g_z[(size_t)N_NODES * D];
__device__ float g_h1[(size_t)N_NODES * D];
__device__ float g_h2[(size_t)N_NODES * D];

// ---------------- index dtype handling ----------------
__device__ __forceinline__ int load_idx(const void* p, int i, int is64) {
    if (is64) return (int)((const unsigned long long*)p)[i];
    return ((const int*)p)[i];
}

__global__ void k_detect(const int* __restrict__ src32) {
    __shared__ int nz;
    if (threadIdx.x == 0) nz = 0;
    __syncthreads();
    int found = 0;
    for (int i = threadIdx.x; i < 4096; i += blockDim.x)
        if (src32[2 * i + 1] != 0) found = 1;
    if (found) atomicOr(&nz, 1);
    __syncthreads();
    if (threadIdx.x == 0) g_is64 = nz ? 0 : 1;
}

__global__ void k_init() {
    int i = blockIdx.x * blockDim.x + threadIdx.x;
    if (i < N_NODES) g_cnt[i] = 0;
}

__global__ void k_hist(const void* __restrict__ dst) {
    int e = blockIdx.x * blockDim.x + threadIdx.x;
    if (e >= N_EDGES) return;
    int is64 = g_is64;
    int d = load_idx(dst, e, is64);
    atomicAdd(&g_cnt[d], 1);
}

__global__ void k_scan1() {
    __shared__ int s[SCAN_BS];
    int tid = threadIdx.x;
    int i = blockIdx.x * SCAN_BS + tid;
    int v = (i < N_NODES) ? g_cnt[i] : 0;
    s[tid] = v;
    __syncthreads();
#pragma unroll
    for (int off = 1; off < SCAN_BS; off <<= 1) {
        int t = (tid >= off) ? s[tid - off] : 0;
        __syncthreads();
        s[tid] += t;
        __syncthreads();
    }
    if (i < N_NODES) g_rowoff[i] = s[tid] - v;
    if (tid == SCAN_BS - 1) g_part[blockIdx.x] = s[SCAN_BS - 1];
}

__global__ void k_scan2() {
    __shared__ int s[256];
    int tid = threadIdx.x;
    int v = (tid < NB_SCAN) ? g_part[tid] : 0;
    s[tid] = v;
    __syncthreads();
#pragma unroll
    for (int off = 1; off < 256; off <<= 1) {
        int t = (tid >= off) ? s[tid - off] : 0;
        __syncthreads();
        s[tid] += t;
        __syncthreads();
    }
    if (tid < NB_SCAN) g_part[tid] = s[tid] - v;
}

__global__ void k_scan3() {
    int i = blockIdx.x * blockDim.x + threadIdx.x;
    if (i < N_NODES) {
        int off = g_rowoff[i] + g_part[i >> 9];
        g_rowoff[i] = off;
        g_cnt[i] = off;
    }
    if (i == 0) g_rowoff[N_NODES] = N_EDGES;
}

__global__ void k_scatter(const void* __restrict__ src, const void* __restrict__ dst) {
    int e = blockIdx.x * blockDim.x + threadIdx.x;
    if (e >= N_EDGES) return;
    int is64 = g_is64;
    int s = load_idx(src, e, is64);
    int d = load_idx(dst, e, is64);
    int pos = atomicAdd(&g_cnt[d], 1);
    g_adj[pos] = s;
}

// t[node] = (1+eps)*h[node] + sum_{e: dst==node} h[src[e]]
__global__ void __launch_bounds__(256) k_agg(const float* __restrict__ h,
                                             const float* __restrict__ eps_p,
                                             float* __restrict__ outt) {
    int w = blockIdx.x * 8 + (threadIdx.x >> 5);
    int lane = threadIdx.x & 31;
    if (w >= N_NODES) return;
    float ep1 = 1.0f + *eps_p;
    const float4* h4 = (const float4*)h;
    float4 a0 = make_float4(0.f, 0.f, 0.f, 0.f);
    float4 a1 = make_float4(0.f, 0.f, 0.f, 0.f);
    int e = g_rowoff[w];
    int end = g_rowoff[w + 1];
    for (; e + 2 <= end; e += 2) {
        int s0 = g_adj[e], s1 = g_adj[e + 1];
        float4 v0 = h4[(size_t)s0 * 32 + lane];
        float4 v1 = h4[(size_t)s1 * 32 + lane];
        a0.x += v0.x; a0.y += v0.y; a0.z += v0.z; a0.w += v0.w;
        a1.x += v1.x; a1.y += v1.y; a1.z += v1.z; a1.w += v1.w;
    }
    if (e < end) {
        int s0 = g_adj[e];
        float4 v0 = h4[(size_t)s0 * 32 + lane];
        a0.x += v0.x; a0.y += v0.y; a0.z += v0.z; a0.w += v0.w;
    }
    float4 self = h4[(size_t)w * 32 + lane];
    float4 r;
    r.x = ep1 * self.x + a0.x + a1.x;
    r.y = ep1 * self.y + a0.y + a1.y;
    r.z = ep1 * self.z + a0.z + a1.z;
    r.w = ep1 * self.w + a0.w + a1.w;
    ((float4*)outt)[(size_t)w * 32 + lane] = r;
}

// ================= mma.sync fp16 2-term split GEMM =================
// C[M, 128-slice of LDN] = epilogue(A[M,128] @ W[128,LDN])
// A split into fp16 hi/lo (exact residual), B = fp16(W).
// D = Ahi*B + Alo*B (fp32 accum). Error source: B fp16 rounding (~2^-12 norm).
// Block: 128x128 tile, 256 threads (8 warps as 2x4), warp tile 64x32.
// Fragments via ldmatrix (A: m8n8.x4, B: m8n8.x4.trans).
// SMEM: A_hi [128m][128k], A_lo, B [128k][128n]; 272 B row stride
// (17 x 16B chunks, coprime with 32 banks -> ldmatrix conflict-free).
#define PADB 272
#define SA_HI 0
#define SA_LO 34816
#define SB    69632
#define SMEM_GEMM 104448

__device__ __forceinline__ uint32_t smem_u32(const void* p) {
    uint32_t a;
    asm("{ .reg .u64 t; cvta.to.shared.u64 t, %1; cvt.u32.u64 %0, t; }" : "=r"(a) : "l"(p));
    return a;
}

__device__ __forceinline__ void mma16816h(float* c, const uint32_t* a, const uint32_t* b) {
    asm volatile(
        "mma.sync.aligned.m16n8k16.row.col.f32.f16.f16.f32 "
        "{%0,%1,%2,%3}, {%4,%5,%6,%7}, {%8,%9}, {%0,%1,%2,%3};"
        : "+f"(c[0]), "+f"(c[1]), "+f"(c[2]), "+f"(c[3])
        : "r"(a[0]), "r"(a[1]), "r"(a[2]), "r"(a[3]), "r"(b[0]), "r"(b[1]));
}
#define LDMATRIX_X4(r0, r1, r2, r3, addr) \
    asm volatile("ldmatrix.sync.aligned.m8n8.x4.shared.b16 {%0,%1,%2,%3}, [%4];" \
        : "=r"(r0), "=r"(r1), "=r"(r2), "=r"(r3) : "r"(addr))
#define LDMATRIX_X4_T(r0, r1, r2, r3, addr) \
    asm volatile("ldmatrix.sync.aligned.m8n8.x4.trans.shared.b16 {%0,%1,%2,%3}, [%4];" \
        : "=r"(r0), "=r"(r1), "=r"(r2), "=r"(r3) : "r"(addr))

__device__ __forceinline__ uint32_t h2_as_u32(__half2 h) {
    return *reinterpret_cast<uint32_t*>(&h);
}

template <int RELU, int ADDSRC, int POOL, int LDN>
__global__ void __launch_bounds__(256, 2) k_gemm_mma(const float* __restrict__ A,
                                                     const float* __restrict__ A2,
                                                     const float* __restrict__ W,
                                                     const float* __restrict__ bias,
                                                     const float* __restrict__ Z,
                                                     float* __restrict__ C, int M) {
    extern __shared__ char sm[];
    const uint32_t smb = smem_u32(sm);
    const int tid = threadIdx.x;
    const int wid = tid >> 5;
    const int lane = tid & 31;
    const int qid = lane >> 2;
    const int qtr = lane & 3;
    const int m0 = blockIdx.x * 128;
    const int n0 = blockIdx.y * 128;
    const int wm = (wid >> 2) * 64;
    const int wn = (wid & 3) * 32;

    // ---- fill A planes: [m][k] fp16 hi + exact-residual lo ----
    {
        const float4* A4 = (const float4*)A;
        const float4* A24 = (const float4*)A2;
#pragma unroll 4
        for (int p = 0; p < 16; p++) {
            int idx = p * 256 + tid;      // 0..4095
            int row = idx >> 5;
            int c4 = idx & 31;
            float4 v = make_float4(0.f, 0.f, 0.f, 0.f);
            if (m0 + row < M) {
                size_t gi = (size_t)(m0 + row) * 32 + c4;
                v = A4[gi];
                if (POOL) {
                    float4 u = A24[gi];
                    v.x = 0.5f * (v.x + u.x);
                    v.y = 0.5f * (v.y + u.y);
                    v.z = 0.5f * (v.z + u.z);
                    v.w = 0.5f * (v.w + u.w);
                }
            }
            __half2 h01 = __float22half2_rn(make_float2(v.x, v.y));
            __half2 h23 = __float22half2_rn(make_float2(v.z, v.w));
            float2 f01 = __half22float2(h01);
            float2 f23 = __half22float2(h23);
            __half2 l01 = __float22half2_rn(make_float2(v.x - f01.x, v.y - f01.y));
            __half2 l23 = __float22half2_rn(make_float2(v.z - f23.x, v.w - f23.y));
            uint2 hp = make_uint2(h2_as_u32(h01), h2_as_u32(h23));
            uint2 lp = make_uint2(h2_as_u32(l01), h2_as_u32(l23));
            *(uint2*)(sm + SA_HI + row * PADB + c4 * 8) = hp;
            *(uint2*)(sm + SA_LO + row * PADB + c4 * 8) = lp;
        }
    }
    // ---- fill B plane: [k][n] fp16 from W[k][n0..n0+127] ----
    {
#pragma unroll 4
        for (int p = 0; p < 16; p++) {
            int idx = p * 256 + tid;      // 0..4095
            int k = idx >> 5;
            int c4 = idx & 31;
            float4 w = *(const float4*)(W + (size_t)k * LDN + n0 + c4 * 4);
            __half2 h01 = __float22half2_rn(make_float2(w.x, w.y));
            __half2 h23 = __float22half2_rn(make_float2(w.z, w.w));
            uint2 hp = make_uint2(h2_as_u32(h01), h2_as_u32(h23));
            *(uint2*)(sm + SB + k * PADB + c4 * 8) = hp;
        }
    }
    __syncthreads();

    float acc[4][4][4];
#pragma unroll
    for (int i = 0; i < 4; i++)
#pragma unroll
        for (int j = 0; j < 4; j++)
#pragma unroll
            for (int r = 0; r < 4; r++) acc[i][j][r] = 0.f;

    // per-lane ldmatrix source addresses
    const int lr = (lane & 7) + 8 * ((lane >> 3) & 1);  // 0..15 (row within 16)
    const int lh = lane >> 4;                            // 0..1  (k/n half)
    const uint32_t aBase = smb + SA_HI + (uint32_t)(wm + lr) * PADB + (uint32_t)(lh * 8) * 2;
    const uint32_t bBase = smb + SB + (uint32_t)lr * PADB + (uint32_t)(wn + lh * 8) * 2;

#pragma unroll
    for (int ks = 0; ks < 8; ks++) {
        const int kb = ks * 16;
        uint32_t b[4][2];
#pragma unroll
        for (int jj = 0; jj < 2; jj++) {
            uint32_t r0, r1, r2, r3;
            LDMATRIX_X4_T(r0, r1, r2, r3, bBase + (uint32_t)kb * PADB + jj * 32);
            b[2 * jj][0] = r0; b[2 * jj][1] = r1;
            b[2 * jj + 1][0] = r2; b[2 * jj + 1][1] = r3;
        }
#pragma unroll
        for (int i = 0; i < 4; i++) {
            uint32_t ah[4], al[4];
            uint32_t addr = aBase + (uint32_t)(i * 16 * PADB) + (uint32_t)kb * 2;
            LDMATRIX_X4(ah[0], ah[1], ah[2], ah[3], addr);
            LDMATRIX_X4(al[0], al[1], al[2], al[3], addr + (SA_LO - SA_HI));
#pragma unroll
            for (int j = 0; j < 4; j++) {
                mma16816h(acc[i][j], ah, b[j]);   // hi * B
                mma16816h(acc[i][j], al, b[j]);   // lo * B
            }
        }
    }

    // ---- epilogue: bias (+relu) (+residual add), direct global store ----
#pragma unroll
    for (int i = 0; i < 4; i++) {
#pragma unroll
        for (int h = 0; h < 2; h++) {
            int row = m0 + wm + i * 16 + h * 8 + qid;
            if (row >= M) continue;
#pragma unroll
            for (int j = 0; j < 4; j++) {
                int col = n0 + wn + j * 8 + qtr * 2;
                float v0 = acc[i][j][h * 2 + 0] + bias[col];
                float v1 = acc[i][j][h * 2 + 1] + bias[col + 1];
                if (RELU) {
                    v0 = fmaxf(v0, 0.f);
                    v1 = fmaxf(v1, 0.f);
                }
                if (ADDSRC) {
                    float2 z = *(const float2*)(Z + (size_t)row * LDN + col);
                    v0 += z.x;
                    v1 += z.y;
                }
                float2 st = make_float2(v0, v1);
                *(float2*)(C + (size_t)row * LDN + col) = st;
            }
        }
    }
}

// ---------------- launcher ----------------
extern "C" void kernel_launch(void* const* d_in, const int* in_sizes, int n_in,
                              void* d_out, int out_size) {
    const float* inputs = (const float*)d_in[0];
    const void*  src    = d_in[1];
    const void*  dst    = d_in[2];
    const float* eps1   = (const float*)d_in[3];
    const float* W1     = (const float*)d_in[4];
    const float* b1     = (const float*)d_in[5];
    const float* rW1    = (const float*)d_in[6];
    const float* rb1    = (const float*)d_in[7];
    const float* eps2   = (const float*)d_in[8];
    const float* W2     = (const float*)d_in[9];
    const float* b2     = (const float*)d_in[10];
    const float* rW2    = (const float*)d_in[11];
    const float* rb2    = (const float*)d_in[12];
    const float* linW   = (const float*)d_in[13];
    const float* linb   = (const float*)d_in[14];
    float* out = (float*)d_out;

    float *t, *z, *h1, *h2;
    cudaGetSymbolAddress((void**)&t,  g_t);
    cudaGetSymbolAddress((void**)&z,  g_z);
    cudaGetSymbolAddress((void**)&h1, g_h1);
    cudaGetSymbolAddress((void**)&h2, g_h2);

    const int M = N_NODES;
    const int EB = (N_EDGES + 255) / 256;
    const int NBn = (N_NODES + 255) / 256;

    cudaFuncSetAttribute(k_gemm_mma<1, 0, 0, 128>,
                         cudaFuncAttributeMaxDynamicSharedMemorySize, SMEM_GEMM);
    cudaFuncSetAttribute(k_gemm_mma<1, 1, 0, 128>,
                         cudaFuncAttributeMaxDynamicSharedMemorySize, SMEM_GEMM);
    cudaFuncSetAttribute(k_gemm_mma<0, 0, 1, NLAB>,
                         cudaFuncAttributeMaxDynamicSharedMemorySize, SMEM_GEMM);

    // CSR build
    k_init<<<NBn, 256>>>();
    k_detect<<<1, 256>>>((const int*)src);
    k_hist<<<EB, 256>>>(dst);
    k_scan1<<<NB_SCAN, SCAN_BS>>>();
    k_scan2<<<1, 256>>>();
    k_scan3<<<NBn, 256>>>();
    k_scatter<<<EB, 256>>>(src, dst);

    const int AGG_B = (N_NODES + 7) / 8;
    const int GM = (M + 127) / 128;   // 782

    // Layer 1
    k_agg<<<AGG_B, 256>>>(inputs, eps1, t);
    k_gemm_mma<1, 0, 0, 128><<<dim3(GM, 1), 256, SMEM_GEMM>>>(t, nullptr, W1, b1, nullptr, z, M);
    k_gemm_mma<1, 1, 0, 128><<<dim3(GM, 1), 256, SMEM_GEMM>>>(z, nullptr, rW1, rb1, z, h1, M);
    // Layer 2
    k_agg<<<AGG_B, 256>>>(h1, eps2, t);
    k_gemm_mma<1, 0, 0, 128><<<dim3(GM, 1), 256, SMEM_GEMM>>>(t, nullptr, W2, b2, nullptr, z, M);
    k_gemm_mma<1, 1, 0, 128><<<dim3(GM, 1), 256, SMEM_GEMM>>>(z, nullptr, rW2, rb2, z, h2, M);
    // Pool + head: out = 0.5*(h1+h2) @ linW + linb
    k_gemm_mma<0, 0, 1, NLAB><<<dim3(GM, NLAB / 128), 256, SMEM_GEMM>>>(h1, h2, linW, linb, nullptr, out, M);
}

// round 17
// speedup vs baseline: 2.0324x; 1.2215x over previous
#include <cuda_runtime.h>
#include <cuda_fp16.h>
#include <cstdint>

#define N_NODES 100000
#define N_EDGES 1600000
#define D 128
#define NLAB 1024
#define SCAN_BS 512
#define NB_SCAN ((N_NODES + SCAN_BS - 1) / SCAN_BS)   // 196

// ---------------- device scratch (no allocations allowed) ----------------
__device__ int   g_is64;
__device__ int   g_cnt[N_NODES];
__device__ int   g_rowoff[N_NODES + 1];
__device__ int   g_part[256];
__device__ int   g_adj[N_EDGES];
__device__ float g_t[(size_t)N_NODES * D];
__device__ float g_h1[(size_t)N_NODES * D];
__device__ uint32_t g_phi[(size_t)N_NODES * 64];   // pooled fp16 hi plane
__device__ uint32_t g_plo[(size_t)N_NODES * 64];   // pooled fp16 lo plane

// ---------------- index dtype handling ----------------
__device__ __forceinline__ int load_idx(const void* p, int i, int is64) {
    if (is64) return (int)((const unsigned long long*)p)[i];
    return ((const int*)p)[i];
}

__global__ void k_detect(const int* __restrict__ src32) {
    __shared__ int nz;
    if (threadIdx.x == 0) nz = 0;
    __syncthreads();
    int found = 0;
    for (int i = threadIdx.x; i < 4096; i += blockDim.x)
        if (src32[2 * i + 1] != 0) found = 1;
    if (found) atomicOr(&nz, 1);
    __syncthreads();
    if (threadIdx.x == 0) g_is64 = nz ? 0 : 1;
}

__global__ void k_init() {
    int i = blockIdx.x * blockDim.x + threadIdx.x;
    if (i < N_NODES) g_cnt[i] = 0;
}

__global__ void k_hist(const void* __restrict__ dst) {
    int e = blockIdx.x * blockDim.x + threadIdx.x;
    if (e >= N_EDGES) return;
    int is64 = g_is64;
    int d = load_idx(dst, e, is64);
    atomicAdd(&g_cnt[d], 1);
}

__global__ void k_scan1() {
    __shared__ int s[SCAN_BS];
    int tid = threadIdx.x;
    int i = blockIdx.x * SCAN_BS + tid;
    int v = (i < N_NODES) ? g_cnt[i] : 0;
    s[tid] = v;
    __syncthreads();
#pragma unroll
    for (int off = 1; off < SCAN_BS; off <<= 1) {
        int t = (tid >= off) ? s[tid - off] : 0;
        __syncthreads();
        s[tid] += t;
        __syncthreads();
    }
    if (i < N_NODES) g_rowoff[i] = s[tid] - v;
    if (tid == SCAN_BS - 1) g_part[blockIdx.x] = s[SCAN_BS - 1];
}

__global__ void k_scan2() {
    __shared__ int s[256];
    int tid = threadIdx.x;
    int v = (tid < NB_SCAN) ? g_part[tid] : 0;
    s[tid] = v;
    __syncthreads();
#pragma unroll
    for (int off = 1; off < 256; off <<= 1) {
        int t = (tid >= off) ? s[tid - off] : 0;
        __syncthreads();
        s[tid] += t;
        __syncthreads();
    }
    if (tid < NB_SCAN) g_part[tid] = s[tid] - v;
}

__global__ void k_scan3() {
    int i = blockIdx.x * blockDim.x + threadIdx.x;
    if (i < N_NODES) {
        int off = g_rowoff[i] + g_part[i >> 9];
        g_rowoff[i] = off;
        g_cnt[i] = off;
    }
    if (i == 0) g_rowoff[N_NODES] = N_EDGES;
}

__global__ void k_scatter(const void* __restrict__ src, const void* __restrict__ dst) {
    int e = blockIdx.x * blockDim.x + threadIdx.x;
    if (e >= N_EDGES) return;
    int is64 = g_is64;
    int s = load_idx(src, e, is64);
    int d = load_idx(dst, e, is64);
    int pos = atomicAdd(&g_cnt[d], 1);
    g_adj[pos] = s;
}

// t[node] = (1+eps)*h[node] + sum_{e: dst==node} h[src[e]]
__global__ void __launch_bounds__(256) k_agg(const float* __restrict__ h,
                                             const float* __restrict__ eps_p,
                                             float* __restrict__ outt) {
    int w = blockIdx.x * 8 + (threadIdx.x >> 5);
    int lane = threadIdx.x & 31;
    if (w >= N_NODES) return;
    float ep1 = 1.0f + *eps_p;
    const float4* h4 = (const float4*)h;
    float4 a0 = make_float4(0.f, 0.f, 0.f, 0.f);
    float4 a1 = make_float4(0.f, 0.f, 0.f, 0.f);
    int e = g_rowoff[w];
    int end = g_rowoff[w + 1];
    for (; e + 2 <= end; e += 2) {
        int s0 = g_adj[e], s1 = g_adj[e + 1];
        float4 v0 = h4[(size_t)s0 * 32 + lane];
        float4 v1 = h4[(size_t)s1 * 32 + lane];
        a0.x += v0.x; a0.y += v0.y; a0.z += v0.z; a0.w += v0.w;
        a1.x += v1.x; a1.y += v1.y; a1.z += v1.z; a1.w += v1.w;
    }
    if (e < end) {
        int s0 = g_adj[e];
        float4 v0 = h4[(size_t)s0 * 32 + lane];
        a0.x += v0.x; a0.y += v0.y; a0.z += v0.z; a0.w += v0.w;
    }
    float4 self = h4[(size_t)w * 32 + lane];
    float4 r;
    r.x = ep1 * self.x + a0.x + a1.x;
    r.y = ep1 * self.y + a0.y + a1.y;
    r.z = ep1 * self.z + a0.z + a1.z;
    r.w = ep1 * self.w + a0.w + a1.w;
    ((float4*)outt)[(size_t)w * 32 + lane] = r;
}

// ================= shared GEMM machinery (fp16 2-term split, ldmatrix) ======
#define PADB 272
#define SA_HI 0
#define SA_LO 34816
#define SB    69632
#define SMEM_GEMM 104448

__device__ __forceinline__ uint32_t smem_u32(const void* p) {
    uint32_t a;
    asm("{ .reg .u64 t; cvta.to.shared.u64 t, %1; cvt.u32.u64 %0, t; }" : "=r"(a) : "l"(p));
    return a;
}
__device__ __forceinline__ void mma16816h(float* c, const uint32_t* a, const uint32_t* b) {
    asm volatile(
        "mma.sync.aligned.m16n8k16.row.col.f32.f16.f16.f32 "
        "{%0,%1,%2,%3}, {%4,%5,%6,%7}, {%8,%9}, {%0,%1,%2,%3};"
        : "+f"(c[0]), "+f"(c[1]), "+f"(c[2]), "+f"(c[3])
        : "r"(a[0]), "r"(a[1]), "r"(a[2]), "r"(a[3]), "r"(b[0]), "r"(b[1]));
}
#define LDMATRIX_X4(r0, r1, r2, r3, addr) \
    asm volatile("ldmatrix.sync.aligned.m8n8.x4.shared.b16 {%0,%1,%2,%3}, [%4];" \
        : "=r"(r0), "=r"(r1), "=r"(r2), "=r"(r3) : "r"(addr))
#define LDMATRIX_X4_T(r0, r1, r2, r3, addr) \
    asm volatile("ldmatrix.sync.aligned.m8n8.x4.trans.shared.b16 {%0,%1,%2,%3}, [%4];" \
        : "=r"(r0), "=r"(r1), "=r"(r2), "=r"(r3) : "r"(addr))
__device__ __forceinline__ uint32_t h2_as_u32(__half2 h) {
    return *reinterpret_cast<uint32_t*>(&h);
}

// mainloop over K=128: acc += Ahi@B + Alo@B  (A planes at SA_HI/SA_LO, B at SB)
__device__ __forceinline__ void gemm_mainloop(uint32_t aBase, uint32_t bBase,
                                              float acc[4][4][4]) {
#pragma unroll
    for (int ks = 0; ks < 8; ks++) {
        const int kb = ks * 16;
        uint32_t b[4][2];
#pragma unroll
        for (int jj = 0; jj < 2; jj++) {
            uint32_t r0, r1, r2, r3;
            LDMATRIX_X4_T(r0, r1, r2, r3, bBase + (uint32_t)kb * PADB + jj * 32);
            b[2 * jj][0] = r0; b[2 * jj][1] = r1;
            b[2 * jj + 1][0] = r2; b[2 * jj + 1][1] = r3;
        }
#pragma unroll
        for (int i = 0; i < 4; i++) {
            uint32_t ah[4], al[4];
            uint32_t addr = aBase + (uint32_t)(i * 16 * PADB) + (uint32_t)kb * 2;
            LDMATRIX_X4(ah[0], ah[1], ah[2], ah[3], addr);
            LDMATRIX_X4(al[0], al[1], al[2], al[3], addr + (SA_LO - SA_HI));
#pragma unroll
            for (int j = 0; j < 4; j++) {
                mma16816h(acc[i][j], ah, b[j]);
                mma16816h(acc[i][j], al, b[j]);
            }
        }
    }
}

// fill B plane [k][n(128)] fp16 from fp32 W slice
template <int LDN>
__device__ __forceinline__ void fill_B(char* sm, const float* W, int n0, int tid) {
#pragma unroll 4
    for (int p = 0; p < 16; p++) {
        int idx = p * 256 + tid;
        int k = idx >> 5;
        int c4 = idx & 31;
        float4 w = *(const float4*)(W + (size_t)k * LDN + n0 + c4 * 4);
        __half2 h01 = __float22half2_rn(make_float2(w.x, w.y));
        __half2 h23 = __float22half2_rn(make_float2(w.z, w.w));
        *(uint2*)(sm + SB + k * PADB + c4 * 8) = make_uint2(h2_as_u32(h01), h2_as_u32(h23));
    }
}

// ================= fused GIN layer: z=relu(T@W+b); h=z+relu(z@rW+rb)
// WRPOOL=0: write h to Hout.  WRPOOL=1: write pooled fp16 planes 0.5*(h+Hprev).
template <int WRPOOL>
__global__ void __launch_bounds__(256, 2) k_gin_layer(const float* __restrict__ T,
                                                      const float* __restrict__ W,
                                                      const float* __restrict__ bias,
                                                      const float* __restrict__ rW,
                                                      const float* __restrict__ rbias,
                                                      float* __restrict__ Hout,
                                                      const float* __restrict__ Hprev,
                                                      uint32_t* __restrict__ Phi,
                                                      uint32_t* __restrict__ Plo,
                                                      int M) {
    extern __shared__ char sm[];
    const uint32_t smb = smem_u32(sm);
    const int tid = threadIdx.x;
    const int wid = tid >> 5;
    const int lane = tid & 31;
    const int qid = lane >> 2;
    const int qtr = lane & 3;
    const int m0 = blockIdx.x * 128;
    const int wm = (wid >> 2) * 64;
    const int wn = (wid & 3) * 32;

    // ---- phase-1 A fill from T (fp32 -> fp16 hi/lo) ----
    {
        const float4* A4 = (const float4*)T;
#pragma unroll 4
        for (int p = 0; p < 16; p++) {
            int idx = p * 256 + tid;
            int row = idx >> 5;
            int c4 = idx & 31;
            float4 v = make_float4(0.f, 0.f, 0.f, 0.f);
            if (m0 + row < M) v = A4[(size_t)(m0 + row) * 32 + c4];
            __half2 h01 = __float22half2_rn(make_float2(v.x, v.y));
            __half2 h23 = __float22half2_rn(make_float2(v.z, v.w));
            float2 f01 = __half22float2(h01);
            float2 f23 = __half22float2(h23);
            __half2 l01 = __float22half2_rn(make_float2(v.x - f01.x, v.y - f01.y));
            __half2 l23 = __float22half2_rn(make_float2(v.z - f23.x, v.w - f23.y));
            *(uint2*)(sm + SA_HI + row * PADB + c4 * 8) = make_uint2(h2_as_u32(h01), h2_as_u32(h23));
            *(uint2*)(sm + SA_LO + row * PADB + c4 * 8) = make_uint2(h2_as_u32(l01), h2_as_u32(l23));
        }
    }
    fill_B<128>(sm, W, 0, tid);
    __syncthreads();

    float acc[4][4][4];
#pragma unroll
    for (int i = 0; i < 4; i++)
#pragma unroll
        for (int j = 0; j < 4; j++)
#pragma unroll
            for (int r = 0; r < 4; r++) acc[i][j][r] = 0.f;

    const int lr = (lane & 7) + 8 * ((lane >> 3) & 1);
    const int lh = lane >> 4;
    const uint32_t aBase = smb + SA_HI + (uint32_t)(wm + lr) * PADB + (uint32_t)(lh * 8) * 2;
    const uint32_t bBase = smb + SB + (uint32_t)lr * PADB + (uint32_t)(lh * 8) * 2 + (uint32_t)wn * 2;

    gemm_mainloop(aBase, bBase, acc);

    // z = relu(acc + b)  (in registers)
#pragma unroll
    for (int i = 0; i < 4; i++)
#pragma unroll
        for (int j = 0; j < 4; j++) {
            int col = wn + j * 8 + qtr * 2;
            float b0 = bias[col], b1v = bias[col + 1];
            acc[i][j][0] = fmaxf(acc[i][j][0] + b0, 0.f);
            acc[i][j][1] = fmaxf(acc[i][j][1] + b1v, 0.f);
            acc[i][j][2] = fmaxf(acc[i][j][2] + b0, 0.f);
            acc[i][j][3] = fmaxf(acc[i][j][3] + b1v, 0.f);
        }
    __syncthreads();   // phase-1 reads of A/B done

    // ---- store z into SMEM A planes (fp16 hi/lo), refill B with rW ----
#pragma unroll
    for (int i = 0; i < 4; i++)
#pragma unroll
        for (int h = 0; h < 2; h++) {
            int row = wm + i * 16 + h * 8 + qid;
#pragma unroll
            for (int j = 0; j < 4; j++) {
                int colw = (wn >> 1) + j * 4 + qtr;
                float z0 = acc[i][j][h * 2 + 0];
                float z1 = acc[i][j][h * 2 + 1];
                __half2 hh = __floats2half2_rn(z0, z1);
                float2 f = __half22float2(hh);
                __half2 ll = __floats2half2_rn(z0 - f.x, z1 - f.y);
                *(uint32_t*)(sm + SA_HI + row * PADB + colw * 4) = h2_as_u32(hh);
                *(uint32_t*)(sm + SA_LO + row * PADB + colw * 4) = h2_as_u32(ll);
            }
        }
    fill_B<128>(sm, rW, 0, tid);
    __syncthreads();

#pragma unroll
    for (int i = 0; i < 4; i++)
#pragma unroll
        for (int j = 0; j < 4; j++)
#pragma unroll
            for (int r = 0; r < 4; r++) acc[i][j][r] = 0.f;

    gemm_mainloop(aBase, bBase, acc);

    // ---- epilogue: h = z + relu(acc + rb); write h or pooled fp16 planes ----
#pragma unroll
    for (int i = 0; i < 4; i++)
#pragma unroll
        for (int h = 0; h < 2; h++) {
            int rowl = wm + i * 16 + h * 8 + qid;
            int row = m0 + rowl;
            if (row >= M) continue;
#pragma unroll
            for (int j = 0; j < 4; j++) {
                int col = wn + j * 8 + qtr * 2;
                int colw = col >> 1;
                __half2 zh = *(__half2*)(sm + SA_HI + rowl * PADB + colw * 4);
                __half2 zl = *(__half2*)(sm + SA_LO + rowl * PADB + colw * 4);
                float2 zf = __half22float2(zh);
                float2 zg = __half22float2(zl);
                float z0 = zf.x + zg.x, z1 = zf.y + zg.y;
                float v0 = z0 + fmaxf(acc[i][j][h * 2 + 0] + rbias[col], 0.f);
                float v1 = z1 + fmaxf(acc[i][j][h * 2 + 1] + rbias[col + 1], 0.f);
                if (WRPOOL) {
                    float2 hp = *(const float2*)(Hprev + (size_t)row * 128 + col);
                    float p0 = 0.5f * (v0 + hp.x);
                    float p1 = 0.5f * (v1 + hp.y);
                    __half2 hh = __floats2half2_rn(p0, p1);
                    float2 f = __half22float2(hh);
                    __half2 ll = __floats2half2_rn(p0 - f.x, p1 - f.y);
                    Phi[(size_t)row * 64 + colw] = h2_as_u32(hh);
                    Plo[(size_t)row * 64 + colw] = h2_as_u32(ll);
                } else {
                    *(float2*)(Hout + (size_t)row * 128 + col) = make_float2(v0, v1);
                }
            }
        }
}

// ================= head GEMM: out = pooled(fp16 planes) @ linW + linb =======
__global__ void __launch_bounds__(256, 2) k_head(const uint32_t* __restrict__ Phi,
                                                 const uint32_t* __restrict__ Plo,
                                                 const float* __restrict__ W,
                                                 const float* __restrict__ bias,
                                                 float* __restrict__ C, int M) {
    extern __shared__ char sm[];
    const uint32_t smb = smem_u32(sm);
    const int tid = threadIdx.x;
    const int wid = tid >> 5;
    const int lane = tid & 31;
    const int qid = lane >> 2;
    const int qtr = lane & 3;
    const int m0 = blockIdx.x * 128;
    const int n0 = blockIdx.y * 128;
    const int wm = (wid >> 2) * 64;
    const int wn = (wid & 3) * 32;

    // ---- A fill: copy pre-split fp16 planes ----
#pragma unroll 4
    for (int p = 0; p < 16; p++) {
        int idx = p * 256 + tid;
        int row = idx >> 5;
        int cw = idx & 31;              // uint2 chunk (2 words = 4 halves)
        uint2 hv = make_uint2(0u, 0u), lv = make_uint2(0u, 0u);
        if (m0 + row < M) {
            hv = *(const uint2*)(Phi + (size_t)(m0 + row) * 64 + cw * 2);
            lv = *(const uint2*)(Plo + (size_t)(m0 + row) * 64 + cw * 2);
        }
        *(uint2*)(sm + SA_HI + row * PADB + cw * 8) = hv;
        *(uint2*)(sm + SA_LO + row * PADB + cw * 8) = lv;
    }
    fill_B<NLAB>(sm, W, n0, tid);
    __syncthreads();

    float acc[4][4][4];
#pragma unroll
    for (int i = 0; i < 4; i++)
#pragma unroll
        for (int j = 0; j < 4; j++)
#pragma unroll
            for (int r = 0; r < 4; r++) acc[i][j][r] = 0.f;

    const int lr = (lane & 7) + 8 * ((lane >> 3) & 1);
    const int lh = lane >> 4;
    const uint32_t aBase = smb + SA_HI + (uint32_t)(wm + lr) * PADB + (uint32_t)(lh * 8) * 2;
    const uint32_t bBase = smb + SB + (uint32_t)lr * PADB + (uint32_t)(lh * 8) * 2 + (uint32_t)wn * 2;

    gemm_mainloop(aBase, bBase, acc);

#pragma unroll
    for (int i = 0; i < 4; i++)
#pragma unroll
        for (int h = 0; h < 2; h++) {
            int row = m0 + wm + i * 16 + h * 8 + qid;
            if (row >= M) continue;
#pragma unroll
            for (int j = 0; j < 4; j++) {
                int col = n0 + wn + j * 8 + qtr * 2;
                float v0 = acc[i][j][h * 2 + 0] + bias[col];
                float v1 = acc[i][j][h * 2 + 1] + bias[col + 1];
                *(float2*)(C + (size_t)row * NLAB + col) = make_float2(v0, v1);
            }
        }
}

// ---------------- launcher ----------------
extern "C" void kernel_launch(void* const* d_in, const int* in_sizes, int n_in,
                              void* d_out, int out_size) {
    const float* inputs = (const float*)d_in[0];
    const void*  src    = d_in[1];
    const void*  dst    = d_in[2];
    const float* eps1   = (const float*)d_in[3];
    const float* W1     = (const float*)d_in[4];
    const float* b1     = (const float*)d_in[5];
    const float* rW1    = (const float*)d_in[6];
    const float* rb1    = (const float*)d_in[7];
    const float* eps2   = (const float*)d_in[8];
    const float* W2     = (const float*)d_in[9];
    const float* b2     = (const float*)d_in[10];
    const float* rW2    = (const float*)d_in[11];
    const float* rb2    = (const float*)d_in[12];
    const float* linW   = (const float*)d_in[13];
    const float* linb   = (const float*)d_in[14];
    float* out = (float*)d_out;

    float *t, *h1;
    uint32_t *phi, *plo;
    cudaGetSymbolAddress((void**)&t,   g_t);
    cudaGetSymbolAddress((void**)&h1,  g_h1);
    cudaGetSymbolAddress((void**)&phi, g_phi);
    cudaGetSymbolAddress((void**)&plo, g_plo);

    const int M = N_NODES;
    const int EB = (N_EDGES + 255) / 256;
    const int NBn = (N_NODES + 255) / 256;

    cudaFuncSetAttribute(k_gin_layer<0>,
                         cudaFuncAttributeMaxDynamicSharedMemorySize, SMEM_GEMM);
    cudaFuncSetAttribute(k_gin_layer<1>,
                         cudaFuncAttributeMaxDynamicSharedMemorySize, SMEM_GEMM);
    cudaFuncSetAttribute(k_head,
                         cudaFuncAttributeMaxDynamicSharedMemorySize, SMEM_GEMM);

    // CSR build
    k_init<<<NBn, 256>>>();
    k_detect<<<1, 256>>>((const int*)src);
    k_hist<<<EB, 256>>>(dst);
    k_scan1<<<NB_SCAN, SCAN_BS>>>();
    k_scan2<<<1, 256>>>();
    k_scan3<<<NBn, 256>>>();
    k_scatter<<<EB, 256>>>(src, dst);

    const int AGG_B = (N_NODES + 7) / 8;
    const int GM = (M + 127) / 128;   // 782

    // Layer 1 (writes h1)
    k_agg<<<AGG_B, 256>>>(inputs, eps1, t);
    k_gin_layer<0><<<GM, 256, SMEM_GEMM>>>(t, W1, b1, rW1, rb1, h1, nullptr, nullptr, nullptr, M);
    // Layer 2 (writes pooled fp16 planes; h2 never materialized)
    k_agg<<<AGG_B, 256>>>(h1, eps2, t);
    k_gin_layer<1><<<GM, 256, SMEM_GEMM>>>(t, W2, b2, rW2, rb2, nullptr, h1, phi, plo, M);
    // Head
    k_head<<<dim3(GM, NLAB / 128), 256, SMEM_GEMM>>>(phi, plo, linW, linb, out, M);
}